// round 4
// baseline (speedup 1.0000x reference)
#include <cuda_runtime.h>

// EMA over time: out[b,0,c] = x[b,0,c]; out[b,t,c] = 0.1*x[b,t,c] + 0.9*out[b,t-1,c]
// Shape (16, 4096, 512) fp32.
//
// Chunked scan with warmup truncation: 0.9^96 ~ 4e-5 << 1e-3 threshold.
// CHUNK=256 (warmup overhead 37.5% of reads), parallelism recovered via
// deep unroll (16 float4 loads in flight per thread).

namespace {
constexpr int T      = 4096;
constexpr int C      = 512;       // channels
constexpr int C4     = C / 4;     // float4 channel groups = 128
constexpr int CHUNK  = 256;       // timesteps per chunk
constexpr int NCHUNK = T / CHUNK; // 16
constexpr int W      = 96;        // warmup steps (0.9^96 ~ 4e-5)
constexpr float A = 0.1f;
constexpr float B = 0.9f;
}

__device__ __forceinline__ void ema_step(float4& carry, const float4 v) {
    carry.x = fmaf(B, carry.x, A * v.x);
    carry.y = fmaf(B, carry.y, A * v.y);
    carry.z = fmaf(B, carry.z, A * v.z);
    carry.w = fmaf(B, carry.w, A * v.w);
}

__device__ __forceinline__ void store_cs(float4* p, const float4 v) {
    // evict-first store: don't let streaming output displace x in L2
    asm volatile("st.global.cs.v4.f32 [%0], {%1,%2,%3,%4};"
                 :: "l"(p), "f"(v.x), "f"(v.y), "f"(v.z), "f"(v.w) : "memory");
}

__global__ __launch_bounds__(C4) void ema_chunk_kernel(
    const float4* __restrict__ x, float4* __restrict__ out)
{
    const int c     = threadIdx.x;       // 0..127 float4 group
    const int chunk = blockIdx.x;        // 0..NCHUNK-1
    const int b     = blockIdx.y;        // 0..15

    const size_t base = (size_t)b * T * C4 + c;
    const int t0 = chunk * CHUNK;

    float4 carry;

    if (chunk == 0) {
        // Exact start: out[0] = x[0]
        carry = x[base];
        store_cs(out + base, carry);
        const float4* xp = x + base;
        float4*       op = out + base;
        #pragma unroll 16
        for (int t = 1; t < CHUNK; ++t) {
            float4 v = xp[(size_t)t * C4];
            ema_step(carry, v);
            store_cs(op + (size_t)t * C4, carry);
        }
    } else {
        // Warmup: reconstruct carry from W steps before the chunk.
        const float4* wp = x + base + (size_t)(t0 - W) * C4;
        carry = wp[0];
        #pragma unroll 16
        for (int i = 1; i < W; ++i) {
            float4 v = wp[(size_t)i * C4];
            ema_step(carry, v);
        }
        // Main: compute and store this chunk.
        const float4* mp = x + base + (size_t)t0 * C4;
        float4*       op = out + base + (size_t)t0 * C4;
        #pragma unroll 16
        for (int t = 0; t < CHUNK; ++t) {
            float4 v = mp[(size_t)t * C4];
            ema_step(carry, v);
            store_cs(op + (size_t)t * C4, carry);
        }
    }
}

extern "C" void kernel_launch(void* const* d_in, const int* in_sizes, int n_in,
                              void* d_out, int out_size)
{
    const float4* x = (const float4*)d_in[0];
    float4* out = (float4*)d_out;
    dim3 grid(NCHUNK, 16);
    ema_chunk_kernel<<<grid, C4>>>(x, out);
}

// round 5
// speedup vs baseline: 1.2515x; 1.2515x over previous
#include <cuda_runtime.h>

// EMA over time: out[b,0,c] = x[b,0,c]; out[b,t,c] = 0.1*x[b,t,c] + 0.9*out[b,t-1,c]
// Shape (16, 4096, 512) fp32.
//
// Chunked scan with warmup truncation: 0.9^80 ~ 2.2e-4 << 1e-3 threshold.
// CHUNK=64 -> 64 chunks/batch -> 1024 blocks (4096 warps). This kernel is
// DRAM-latency-bound; warp count is the binding resource (r1/r2/r4 evidence).
// Warmup windows alias the previous chunk's main region -> L2 hits.

namespace {
constexpr int T      = 4096;
constexpr int C      = 512;       // channels
constexpr int C4     = C / 4;     // float4 channel groups = 128
constexpr int CHUNK  = 64;        // timesteps per chunk
constexpr int NCHUNK = T / CHUNK; // 64
constexpr int W      = 80;        // warmup steps (0.9^80 ~ 2.2e-4)
constexpr float A = 0.1f;
constexpr float B = 0.9f;
}

__device__ __forceinline__ void ema_step(float4& carry, const float4 v) {
    carry.x = fmaf(B, carry.x, A * v.x);
    carry.y = fmaf(B, carry.y, A * v.y);
    carry.z = fmaf(B, carry.z, A * v.z);
    carry.w = fmaf(B, carry.w, A * v.w);
}

__global__ __launch_bounds__(C4) void ema_chunk_kernel(
    const float4* __restrict__ x, float4* __restrict__ out)
{
    const int c     = threadIdx.x;       // 0..127 float4 group
    const int chunk = blockIdx.x;        // 0..NCHUNK-1
    const int b     = blockIdx.y;        // 0..15

    const size_t base = (size_t)b * T * C4 + c;
    const int t0 = chunk * CHUNK;

    float4 carry;

    if (chunk == 0) {
        // Exact start: out[0] = x[0]
        carry = x[base];
        __stcs(out + base, carry);
        const float4* xp = x + base;
        float4*       op = out + base;
        #pragma unroll 8
        for (int t = 1; t < CHUNK; ++t) {
            float4 v = xp[(size_t)t * C4];
            ema_step(carry, v);
            __stcs(op + (size_t)t * C4, carry);
        }
    } else {
        // Warmup: reconstruct carry from W steps before the chunk.
        const float4* wp = x + base + (size_t)(t0 - W) * C4;
        carry = wp[0];
        #pragma unroll 8
        for (int i = 1; i < W; ++i) {
            float4 v = wp[(size_t)i * C4];
            ema_step(carry, v);
        }
        // Main: compute and store this chunk.
        const float4* mp = x + base + (size_t)t0 * C4;
        float4*       op = out + base + (size_t)t0 * C4;
        #pragma unroll 8
        for (int t = 0; t < CHUNK; ++t) {
            float4 v = mp[(size_t)t * C4];
            ema_step(carry, v);
            __stcs(op + (size_t)t * C4, carry);
        }
    }
}

extern "C" void kernel_launch(void* const* d_in, const int* in_sizes, int n_in,
                              void* d_out, int out_size)
{
    const float4* x = (const float4*)d_in[0];
    float4* out = (float4*)d_out;
    dim3 grid(NCHUNK, 16);
    ema_chunk_kernel<<<grid, C4>>>(x, out);
}